// round 3
// baseline (speedup 1.0000x reference)
#include <cuda_runtime.h>
#include <cuda_bf16.h>

#define NN 100000
#define EE 3200000
#define GG 512
#define HH 64

// ---------------- scratch (device globals; no allocations) ----------------
__device__ float4 g_bufT4[NN * 16];   // agg output t = (1+eps)x + sum
__device__ float4 g_bufA4[NN * 16];   // MLP output (pre-BN)
__device__ float4 g_bufB4[NN * 16];   // BN output (next layer input)
__device__ int    g_deg[NN];
__device__ int    g_rowptr[NN + 1];
__device__ int    g_cursor[NN];
__device__ int    g_col[EE];
__device__ int    g_gs[GG];
__device__ int    g_ge[GG];
__device__ float  g_bn[128];          // [0:64) sum, [64:128) sumsq

// ---------------- init ----------------
__global__ void k_init() {
    int i = blockIdx.x * blockDim.x + threadIdx.x;
    if (i < NN) g_deg[i] = 0;
    if (i < GG) { g_gs[i] = -1; g_ge[i] = -1; }
}

// ---------------- CSR build ----------------
__global__ void k_hist(const int* __restrict__ ei) {
    int e = blockIdx.x * blockDim.x + threadIdx.x;
    if (e < EE) atomicAdd(&g_deg[ei[EE + e]], 1);
}

__global__ void k_bounds(const int* __restrict__ batch) {
    int i = blockIdx.x * blockDim.x + threadIdx.x;
    if (i >= NN) return;
    int b = batch[i];
    if (i == 0 || batch[i - 1] != b) g_gs[b] = i;
    if (i == NN - 1 || batch[i + 1] != b) g_ge[b] = i;
}

__global__ void k_scan() {
    __shared__ int sp[1024];
    const int t = threadIdx.x;
    const int CH = (NN + 1023) / 1024;
    int base = t * CH;
    int s = 0;
    for (int i = 0; i < CH; i++) {
        int idx = base + i;
        if (idx < NN) s += g_deg[idx];
    }
    sp[t] = s;
    __syncthreads();
    // Hillis-Steele inclusive scan
    for (int off = 1; off < 1024; off <<= 1) {
        int v = (t >= off) ? sp[t - off] : 0;
        __syncthreads();
        sp[t] += v;
        __syncthreads();
    }
    int run = (t == 0) ? 0 : sp[t - 1];
    for (int i = 0; i < CH; i++) {
        int idx = base + i;
        if (idx < NN) {
            g_rowptr[idx] = run;
            g_cursor[idx] = run;
            run += g_deg[idx];
        }
    }
    if (t == 1023) g_rowptr[NN] = sp[1023];
}

__global__ void k_scatter(const int* __restrict__ ei) {
    int e = blockIdx.x * blockDim.x + threadIdx.x;
    if (e >= EE) return;
    int s = ei[e];
    int d = ei[EE + e];
    int p = atomicAdd(&g_cursor[d], 1);
    g_col[p] = s;
}

// ---------------- aggregation: t = (1+eps)*x + sum_{src in nbr(dst)} x[src] ----------------
// one warp per node; 2 half-warps each gather one neighbor row (16 x float4) at a time
__global__ void k_agg(const float4* __restrict__ xext, int use_ext,
                      const float* __restrict__ epsp) {
    int warp = (blockIdx.x * blockDim.x + threadIdx.x) >> 5;
    if (warp >= NN) return;
    const float4* __restrict__ x = use_ext ? xext : g_bufB4;
    int lane = threadIdx.x & 31;
    int half = lane >> 4;
    int li = lane & 15;
    float e1 = 1.0f + *epsp;

    float4 acc = make_float4(0.f, 0.f, 0.f, 0.f);
    if (half == 0) {
        float4 v = x[warp * 16 + li];
        acc.x = e1 * v.x; acc.y = e1 * v.y; acc.z = e1 * v.z; acc.w = e1 * v.w;
    }
    int s = g_rowptr[warp], e = g_rowptr[warp + 1];
    for (int j = s + half; j < e; j += 2) {
        int src = __ldg(&g_col[j]);
        float4 v = x[src * 16 + li];
        acc.x += v.x; acc.y += v.y; acc.z += v.z; acc.w += v.w;
    }
    acc.x += __shfl_xor_sync(0xffffffff, acc.x, 16);
    acc.y += __shfl_xor_sync(0xffffffff, acc.y, 16);
    acc.z += __shfl_xor_sync(0xffffffff, acc.z, 16);
    acc.w += __shfl_xor_sync(0xffffffff, acc.w, 16);
    if (half == 0) g_bufT4[warp * 16 + li] = acc;
}

// ---------------- zero BN accumulators ----------------
__global__ void k_zerobn() {
    if (threadIdx.x < 128) g_bn[threadIdx.x] = 0.f;
}

// ---------------- fused MLP: out = relu(relu(t@wa+ba)@wb+bb), plus BN partial sums ----
// 64-node tile per block, 256 threads, 4x4 micro-tiles
__global__ __launch_bounds__(256) void k_mlp(const float* __restrict__ wa,
                                             const float* __restrict__ ba,
                                             const float* __restrict__ wb,
                                             const float* __restrict__ bb) {
    __shared__ float sT[64][68];      // transposed tile: sT[k][node] (also reused for midT)
    __shared__ float sW[64 * 64];     // weights (wa then wb)
    __shared__ float sB[64];          // bias
    __shared__ float sRed[16][128];   // BN reduce

    const float* __restrict__ tin = (const float*)g_bufT4;
    float* __restrict__ out = (float*)g_bufA4;

    int tid = threadIdx.x;
    int n0 = blockIdx.x * 64;

    // load input tile (transposed) and wa/ba
    for (int idx = tid; idx < 64 * 64; idx += 256) {
        int r = idx >> 6, k = idx & 63;
        int node = n0 + r;
        float v = (node < NN) ? tin[node * 64 + k] : 0.f;
        sT[k][r] = v;
    }
    for (int idx = tid; idx < 4096; idx += 256) sW[idx] = wa[idx];
    if (tid < 64) sB[tid] = ba[tid];
    __syncthreads();

    int tx = tid & 15;   // channel quad
    int ty = tid >> 4;   // node quad

    float acc[4][4];
#pragma unroll
    for (int i = 0; i < 4; i++)
#pragma unroll
        for (int j = 0; j < 4; j++) acc[i][j] = 0.f;

#pragma unroll 16
    for (int k = 0; k < 64; k++) {
        float4 a = *(const float4*)&sT[k][ty * 4];
        float4 b = *(const float4*)&sW[k * 64 + tx * 4];
        float av[4] = {a.x, a.y, a.z, a.w};
        float bv[4] = {b.x, b.y, b.z, b.w};
#pragma unroll
        for (int i = 0; i < 4; i++)
#pragma unroll
            for (int j = 0; j < 4; j++) acc[i][j] = fmaf(av[i], bv[j], acc[i][j]);
    }
    __syncthreads();  // all reads of sT/sW done

    // mid = relu(acc + ba), stored transposed back into sT
#pragma unroll
    for (int j = 0; j < 4; j++) {
        float bias = sB[4 * tx + j];
        float4 m;
        m.x = fmaxf(acc[0][j] + bias, 0.f);
        m.y = fmaxf(acc[1][j] + bias, 0.f);
        m.z = fmaxf(acc[2][j] + bias, 0.f);
        m.w = fmaxf(acc[3][j] + bias, 0.f);
        *(float4*)&sT[4 * tx + j][4 * ty] = m;
    }
    // load wb/bb
    for (int idx = tid; idx < 4096; idx += 256) sW[idx] = wb[idx];
    if (tid < 64) sB[tid] = bb[tid];
    __syncthreads();

    float acc2[4][4];
#pragma unroll
    for (int i = 0; i < 4; i++)
#pragma unroll
        for (int j = 0; j < 4; j++) acc2[i][j] = 0.f;

#pragma unroll 16
    for (int k = 0; k < 64; k++) {
        float4 a = *(const float4*)&sT[k][ty * 4];
        float4 b = *(const float4*)&sW[k * 64 + tx * 4];
        float av[4] = {a.x, a.y, a.z, a.w};
        float bv[4] = {b.x, b.y, b.z, b.w};
#pragma unroll
        for (int i = 0; i < 4; i++)
#pragma unroll
            for (int j = 0; j < 4; j++) acc2[i][j] = fmaf(av[i], bv[j], acc2[i][j]);
    }

    // out = relu(acc2 + bb), write + BN partials
    float psum[4] = {0.f, 0.f, 0.f, 0.f};
    float psq[4] = {0.f, 0.f, 0.f, 0.f};
#pragma unroll
    for (int i = 0; i < 4; i++) {
        int node = n0 + 4 * ty + i;
        float o[4];
#pragma unroll
        for (int j = 0; j < 4; j++) o[j] = fmaxf(acc2[i][j] + sB[4 * tx + j], 0.f);
        if (node < NN) {
            float4 ov = make_float4(o[0], o[1], o[2], o[3]);
            *(float4*)&out[node * 64 + 4 * tx] = ov;
#pragma unroll
            for (int j = 0; j < 4; j++) {
                psum[j] += o[j];
                psq[j] = fmaf(o[j], o[j], psq[j]);
            }
        }
    }
#pragma unroll
    for (int j = 0; j < 4; j++) {
        sRed[ty][4 * tx + j] = psum[j];
        sRed[ty][64 + 4 * tx + j] = psq[j];
    }
    __syncthreads();
    if (tid < 128) {
        float s = 0.f;
#pragma unroll
        for (int r = 0; r < 16; r++) s += sRed[r][tid];
        atomicAdd(&g_bn[tid], s);
    }
}

// ---------------- BN apply: B = (A - mu) * rsqrt(var+eps) * g + be ----------------
__global__ void k_bnapply(const float* __restrict__ gam, const float* __restrict__ bet) {
    __shared__ float sc[64], sh[64];
    if (threadIdx.x < 64) {
        int c = threadIdx.x;
        float inv = 1.0f / (float)NN;
        float mu = g_bn[c] * inv;
        float var = g_bn[64 + c] * inv - mu * mu;
        float s = gam[c] * rsqrtf(var + 1e-5f);
        sc[c] = s;
        sh[c] = bet[c] - mu * s;
    }
    __syncthreads();
    int i = blockIdx.x * blockDim.x + threadIdx.x;  // float4 index, exactly NN*16
    if (i < NN * 16) {
        float4 v = g_bufA4[i];
        int c0 = (i & 15) * 4;
        v.x = fmaf(v.x, sc[c0 + 0], sh[c0 + 0]);
        v.y = fmaf(v.y, sc[c0 + 1], sh[c0 + 1]);
        v.z = fmaf(v.z, sc[c0 + 2], sh[c0 + 2]);
        v.w = fmaf(v.w, sc[c0 + 3], sh[c0 + 3]);
        g_bufB4[i] = v;
    }
}

// ---------------- fused pooling (mean+max) + FC + log_softmax ----------------
__global__ void k_pool(const float* __restrict__ wfc, const float* __restrict__ bfc,
                       float* __restrict__ outp) {
    int g = blockIdx.x;
    int c = threadIdx.x;  // 64 threads
    __shared__ float sm[128];
    __shared__ float sz[6];
    const float* __restrict__ h = (const float*)g_bufB4;

    int s = g_gs[g], e = g_ge[g];
    if (s >= 0) {
        float sum = 0.f, mx = -3.4e38f;
#pragma unroll 4
        for (int i = s; i <= e; i++) {
            float v = h[i * 64 + c];
            sum += v;
            mx = fmaxf(mx, v);
        }
        float cnt = (float)(e - s + 1);
        sm[c] = sum / cnt;
        sm[64 + c] = mx;
    } else {
        sm[c] = 0.f;
        sm[64 + c] = 0.f;
    }
    __syncthreads();
    if (c < 6) {
        float z = bfc[c];
#pragma unroll 8
        for (int k = 0; k < 128; k++) z = fmaf(sm[k], wfc[k * 6 + c], z);
        sz[c] = z;
    }
    __syncthreads();
    if (c == 0) {
        float m = sz[0];
#pragma unroll
        for (int j = 1; j < 6; j++) m = fmaxf(m, sz[j]);
        float se = 0.f;
#pragma unroll
        for (int j = 0; j < 6; j++) se += expf(sz[j] - m);
        float lse = m + logf(se);
#pragma unroll
        for (int j = 0; j < 6; j++) outp[g * 6 + j] = sz[j] - lse;
    }
}

// ---------------- launch ----------------
extern "C" void kernel_launch(void* const* d_in, const int* in_sizes, int n_in,
                              void* d_out, int out_size) {
    const float* x = (const float*)d_in[0];
    const int* ei = (const int*)d_in[1];
    const int* batch = (const int*)d_in[2];
    const float* w1a = (const float*)d_in[3];
    const float* b1a = (const float*)d_in[4];
    const float* w1b = (const float*)d_in[5];
    const float* b1b = (const float*)d_in[6];
    const float* w2a = (const float*)d_in[7];
    const float* b2a = (const float*)d_in[8];
    const float* w2b = (const float*)d_in[9];
    const float* b2b = (const float*)d_in[10];
    const float* w3a = (const float*)d_in[11];
    const float* b3a = (const float*)d_in[12];
    const float* w3b = (const float*)d_in[13];
    const float* b3b = (const float*)d_in[14];
    const float* eps1 = (const float*)d_in[15];
    const float* g1 = (const float*)d_in[16];
    const float* be1 = (const float*)d_in[17];
    const float* eps2 = (const float*)d_in[18];
    const float* g2 = (const float*)d_in[19];
    const float* be2 = (const float*)d_in[20];
    const float* eps3 = (const float*)d_in[21];
    const float* g3 = (const float*)d_in[22];
    const float* be3 = (const float*)d_in[23];
    const float* eps4 = (const float*)d_in[24];
    const float* g4 = (const float*)d_in[25];
    const float* be4 = (const float*)d_in[26];
    const float* wfc = (const float*)d_in[27];
    const float* bfc = (const float*)d_in[28];
    float* out = (float*)d_out;

    const int NB_N = (NN + 255) / 256;       // 391
    const int NB_E = (EE + 255) / 256;       // 12500
    const int NB_AGG = (NN * 32 + 255) / 256;  // warp per node, 8 warps/block
    const int NB_MLP = (NN + 63) / 64;       // 1563
    const int NB_BN = (NN * 16 + 255) / 256; // 6250

    k_init<<<NB_N, 256>>>();
    k_hist<<<NB_E, 256>>>(ei);
    k_bounds<<<NB_N, 256>>>(batch);
    k_scan<<<1, 1024>>>();
    k_scatter<<<NB_E, 256>>>(ei);

    struct Layer {
        const float *wa, *ba, *wb, *bb, *eps, *g, *be;
    } layers[4] = {
        {w1a, b1a, w1b, b1b, eps1, g1, be1},
        {w2a, b2a, w2b, b2b, eps2, g2, be2},
        {w3a, b3a, w3b, b3b, eps3, g3, be3},
        {w3a, b3a, w3b, b3b, eps4, g4, be4},  // conv4 reuses nn3 weights
    };

    for (int l = 0; l < 4; l++) {
        k_agg<<<NB_AGG, 256>>>((const float4*)x, (l == 0) ? 1 : 0, layers[l].eps);
        k_zerobn<<<1, 128>>>();
        k_mlp<<<NB_MLP, 256>>>(layers[l].wa, layers[l].ba, layers[l].wb, layers[l].bb);
        k_bnapply<<<NB_BN, 256>>>(layers[l].g, layers[l].be);
    }

    k_pool<<<GG, 64>>>(wfc, bfc, out);
}

// round 4
// speedup vs baseline: 1.0016x; 1.0016x over previous
#include <cuda_runtime.h>
#include <cuda_bf16.h>

#define NN 100000
#define EE 3200000
#define GG 512
#define HH 64

// ---------------- scratch (device globals; no allocations) ----------------
__device__ float4 g_bufT4[NN * 16];   // agg output t = (1+eps)x + sum
__device__ float4 g_bufA4[NN * 16];   // MLP output (pre-BN)
__device__ float4 g_bufB4[NN * 16];   // BN output (next layer input)
__device__ int    g_deg[NN];
__device__ int    g_rowptr[NN + 1];
__device__ int    g_cursor[NN];
__device__ int    g_col[EE];
__device__ int    g_gs[GG];
__device__ int    g_ge[GG];
__device__ float  g_bn[128];          // [0:64) sum, [64:128) sumsq

// ---------------- init ----------------
__global__ void k_init() {
    int i = blockIdx.x * blockDim.x + threadIdx.x;
    if (i < NN) g_deg[i] = 0;
    if (i < GG) { g_gs[i] = -1; g_ge[i] = -1; }
}

// ---------------- CSR build ----------------
__global__ void k_hist(const int* __restrict__ ei) {
    int e = blockIdx.x * blockDim.x + threadIdx.x;
    if (e < EE) atomicAdd(&g_deg[ei[EE + e]], 1);
}

__global__ void k_bounds(const int* __restrict__ batch) {
    int i = blockIdx.x * blockDim.x + threadIdx.x;
    if (i >= NN) return;
    int b = batch[i];
    if (i == 0 || batch[i - 1] != b) g_gs[b] = i;
    if (i == NN - 1 || batch[i + 1] != b) g_ge[b] = i;
}

__global__ void k_scan() {
    __shared__ int sp[1024];
    const int t = threadIdx.x;
    const int CH = (NN + 1023) / 1024;
    int base = t * CH;
    int s = 0;
    for (int i = 0; i < CH; i++) {
        int idx = base + i;
        if (idx < NN) s += g_deg[idx];
    }
    sp[t] = s;
    __syncthreads();
    // Hillis-Steele inclusive scan
    for (int off = 1; off < 1024; off <<= 1) {
        int v = (t >= off) ? sp[t - off] : 0;
        __syncthreads();
        sp[t] += v;
        __syncthreads();
    }
    int run = (t == 0) ? 0 : sp[t - 1];
    for (int i = 0; i < CH; i++) {
        int idx = base + i;
        if (idx < NN) {
            g_rowptr[idx] = run;
            g_cursor[idx] = run;
            run += g_deg[idx];
        }
    }
    if (t == 1023) g_rowptr[NN] = sp[1023];
}

__global__ void k_scatter(const int* __restrict__ ei) {
    int e = blockIdx.x * blockDim.x + threadIdx.x;
    if (e >= EE) return;
    int s = ei[e];
    int d = ei[EE + e];
    int p = atomicAdd(&g_cursor[d], 1);
    g_col[p] = s;
}

// ---------------- aggregation: t = (1+eps)*x + sum_{src in nbr(dst)} x[src] ----------------
// one warp per node; 2 half-warps each gather one neighbor row (16 x float4) at a time
__global__ void k_agg(const float4* __restrict__ xext, int use_ext,
                      const float* __restrict__ epsp) {
    int warp = (blockIdx.x * blockDim.x + threadIdx.x) >> 5;
    if (warp >= NN) return;
    const float4* __restrict__ x = use_ext ? xext : g_bufB4;
    int lane = threadIdx.x & 31;
    int half = lane >> 4;
    int li = lane & 15;
    float e1 = 1.0f + *epsp;

    float4 acc = make_float4(0.f, 0.f, 0.f, 0.f);
    if (half == 0) {
        float4 v = x[warp * 16 + li];
        acc.x = e1 * v.x; acc.y = e1 * v.y; acc.z = e1 * v.z; acc.w = e1 * v.w;
    }
    int s = g_rowptr[warp], e = g_rowptr[warp + 1];
    for (int j = s + half; j < e; j += 2) {
        int src = __ldg(&g_col[j]);
        float4 v = x[src * 16 + li];
        acc.x += v.x; acc.y += v.y; acc.z += v.z; acc.w += v.w;
    }
    acc.x += __shfl_xor_sync(0xffffffff, acc.x, 16);
    acc.y += __shfl_xor_sync(0xffffffff, acc.y, 16);
    acc.z += __shfl_xor_sync(0xffffffff, acc.z, 16);
    acc.w += __shfl_xor_sync(0xffffffff, acc.w, 16);
    if (half == 0) g_bufT4[warp * 16 + li] = acc;
}

// ---------------- zero BN accumulators ----------------
__global__ void k_zerobn() {
    if (threadIdx.x < 128) g_bn[threadIdx.x] = 0.f;
}

// ---------------- fused MLP: out = relu(relu(t@wa+ba)@wb+bb), plus BN partial sums ----
// 64-node tile per block, 256 threads, 4x4 micro-tiles
__global__ __launch_bounds__(256) void k_mlp(const float* __restrict__ wa,
                                             const float* __restrict__ ba,
                                             const float* __restrict__ wb,
                                             const float* __restrict__ bb) {
    __shared__ float sT[64][68];      // transposed tile: sT[k][node] (also reused for midT)
    __shared__ float sW[64 * 64];     // weights (wa then wb)
    __shared__ float sB[64];          // bias
    __shared__ float sRed[16][128];   // BN reduce

    const float* __restrict__ tin = (const float*)g_bufT4;
    float* __restrict__ out = (float*)g_bufA4;

    int tid = threadIdx.x;
    int n0 = blockIdx.x * 64;

    // load input tile (transposed) and wa/ba
    for (int idx = tid; idx < 64 * 64; idx += 256) {
        int r = idx >> 6, k = idx & 63;
        int node = n0 + r;
        float v = (node < NN) ? tin[node * 64 + k] : 0.f;
        sT[k][r] = v;
    }
    for (int idx = tid; idx < 4096; idx += 256) sW[idx] = wa[idx];
    if (tid < 64) sB[tid] = ba[tid];
    __syncthreads();

    int tx = tid & 15;   // channel quad
    int ty = tid >> 4;   // node quad

    float acc[4][4];
#pragma unroll
    for (int i = 0; i < 4; i++)
#pragma unroll
        for (int j = 0; j < 4; j++) acc[i][j] = 0.f;

#pragma unroll 16
    for (int k = 0; k < 64; k++) {
        float4 a = *(const float4*)&sT[k][ty * 4];
        float4 b = *(const float4*)&sW[k * 64 + tx * 4];
        float av[4] = {a.x, a.y, a.z, a.w};
        float bv[4] = {b.x, b.y, b.z, b.w};
#pragma unroll
        for (int i = 0; i < 4; i++)
#pragma unroll
            for (int j = 0; j < 4; j++) acc[i][j] = fmaf(av[i], bv[j], acc[i][j]);
    }
    __syncthreads();  // all reads of sT/sW done

    // mid = relu(acc + ba), stored transposed back into sT
#pragma unroll
    for (int j = 0; j < 4; j++) {
        float bias = sB[4 * tx + j];
        float4 m;
        m.x = fmaxf(acc[0][j] + bias, 0.f);
        m.y = fmaxf(acc[1][j] + bias, 0.f);
        m.z = fmaxf(acc[2][j] + bias, 0.f);
        m.w = fmaxf(acc[3][j] + bias, 0.f);
        *(float4*)&sT[4 * tx + j][4 * ty] = m;
    }
    // load wb/bb
    for (int idx = tid; idx < 4096; idx += 256) sW[idx] = wb[idx];
    if (tid < 64) sB[tid] = bb[tid];
    __syncthreads();

    float acc2[4][4];
#pragma unroll
    for (int i = 0; i < 4; i++)
#pragma unroll
        for (int j = 0; j < 4; j++) acc2[i][j] = 0.f;

#pragma unroll 16
    for (int k = 0; k < 64; k++) {
        float4 a = *(const float4*)&sT[k][ty * 4];
        float4 b = *(const float4*)&sW[k * 64 + tx * 4];
        float av[4] = {a.x, a.y, a.z, a.w};
        float bv[4] = {b.x, b.y, b.z, b.w};
#pragma unroll
        for (int i = 0; i < 4; i++)
#pragma unroll
            for (int j = 0; j < 4; j++) acc2[i][j] = fmaf(av[i], bv[j], acc2[i][j]);
    }

    // out = relu(acc2 + bb), write + BN partials
    float psum[4] = {0.f, 0.f, 0.f, 0.f};
    float psq[4] = {0.f, 0.f, 0.f, 0.f};
#pragma unroll
    for (int i = 0; i < 4; i++) {
        int node = n0 + 4 * ty + i;
        float o[4];
#pragma unroll
        for (int j = 0; j < 4; j++) o[j] = fmaxf(acc2[i][j] + sB[4 * tx + j], 0.f);
        if (node < NN) {
            float4 ov = make_float4(o[0], o[1], o[2], o[3]);
            *(float4*)&out[node * 64 + 4 * tx] = ov;
#pragma unroll
            for (int j = 0; j < 4; j++) {
                psum[j] += o[j];
                psq[j] = fmaf(o[j], o[j], psq[j]);
            }
        }
    }
#pragma unroll
    for (int j = 0; j < 4; j++) {
        sRed[ty][4 * tx + j] = psum[j];
        sRed[ty][64 + 4 * tx + j] = psq[j];
    }
    __syncthreads();
    if (tid < 128) {
        float s = 0.f;
#pragma unroll
        for (int r = 0; r < 16; r++) s += sRed[r][tid];
        atomicAdd(&g_bn[tid], s);
    }
}

// ---------------- BN apply: B = (A - mu) * rsqrt(var+eps) * g + be ----------------
__global__ void k_bnapply(const float* __restrict__ gam, const float* __restrict__ bet) {
    __shared__ float sc[64], sh[64];
    if (threadIdx.x < 64) {
        int c = threadIdx.x;
        float inv = 1.0f / (float)NN;
        float mu = g_bn[c] * inv;
        float var = g_bn[64 + c] * inv - mu * mu;
        float s = gam[c] * rsqrtf(var + 1e-5f);
        sc[c] = s;
        sh[c] = bet[c] - mu * s;
    }
    __syncthreads();
    int i = blockIdx.x * blockDim.x + threadIdx.x;  // float4 index, exactly NN*16
    if (i < NN * 16) {
        float4 v = g_bufA4[i];
        int c0 = (i & 15) * 4;
        v.x = fmaf(v.x, sc[c0 + 0], sh[c0 + 0]);
        v.y = fmaf(v.y, sc[c0 + 1], sh[c0 + 1]);
        v.z = fmaf(v.z, sc[c0 + 2], sh[c0 + 2]);
        v.w = fmaf(v.w, sc[c0 + 3], sh[c0 + 3]);
        g_bufB4[i] = v;
    }
}

// ---------------- fused pooling (mean+max) + FC + log_softmax ----------------
__global__ void k_pool(const float* __restrict__ wfc, const float* __restrict__ bfc,
                       float* __restrict__ outp) {
    int g = blockIdx.x;
    int c = threadIdx.x;  // 64 threads
    __shared__ float sm[128];
    __shared__ float sz[6];
    const float* __restrict__ h = (const float*)g_bufB4;

    int s = g_gs[g], e = g_ge[g];
    if (s >= 0) {
        float sum = 0.f, mx = -3.4e38f;
#pragma unroll 4
        for (int i = s; i <= e; i++) {
            float v = h[i * 64 + c];
            sum += v;
            mx = fmaxf(mx, v);
        }
        float cnt = (float)(e - s + 1);
        sm[c] = sum / cnt;
        sm[64 + c] = mx;
    } else {
        sm[c] = 0.f;
        sm[64 + c] = 0.f;
    }
    __syncthreads();
    if (c < 6) {
        float z = bfc[c];
#pragma unroll 8
        for (int k = 0; k < 128; k++) z = fmaf(sm[k], wfc[k * 6 + c], z);
        sz[c] = z;
    }
    __syncthreads();
    if (c == 0) {
        float m = sz[0];
#pragma unroll
        for (int j = 1; j < 6; j++) m = fmaxf(m, sz[j]);
        float se = 0.f;
#pragma unroll
        for (int j = 0; j < 6; j++) se += expf(sz[j] - m);
        float lse = m + logf(se);
#pragma unroll
        for (int j = 0; j < 6; j++) outp[g * 6 + j] = sz[j] - lse;
    }
}

// ---------------- launch ----------------
extern "C" void kernel_launch(void* const* d_in, const int* in_sizes, int n_in,
                              void* d_out, int out_size) {
    const float* x = (const float*)d_in[0];
    const int* ei = (const int*)d_in[1];
    const int* batch = (const int*)d_in[2];
    const float* w1a = (const float*)d_in[3];
    const float* b1a = (const float*)d_in[4];
    const float* w1b = (const float*)d_in[5];
    const float* b1b = (const float*)d_in[6];
    const float* w2a = (const float*)d_in[7];
    const float* b2a = (const float*)d_in[8];
    const float* w2b = (const float*)d_in[9];
    const float* b2b = (const float*)d_in[10];
    const float* w3a = (const float*)d_in[11];
    const float* b3a = (const float*)d_in[12];
    const float* w3b = (const float*)d_in[13];
    const float* b3b = (const float*)d_in[14];
    const float* eps1 = (const float*)d_in[15];
    const float* g1 = (const float*)d_in[16];
    const float* be1 = (const float*)d_in[17];
    const float* eps2 = (const float*)d_in[18];
    const float* g2 = (const float*)d_in[19];
    const float* be2 = (const float*)d_in[20];
    const float* eps3 = (const float*)d_in[21];
    const float* g3 = (const float*)d_in[22];
    const float* be3 = (const float*)d_in[23];
    const float* eps4 = (const float*)d_in[24];
    const float* g4 = (const float*)d_in[25];
    const float* be4 = (const float*)d_in[26];
    const float* wfc = (const float*)d_in[27];
    const float* bfc = (const float*)d_in[28];
    float* out = (float*)d_out;

    const int NB_N = (NN + 255) / 256;       // 391
    const int NB_E = (EE + 255) / 256;       // 12500
    const int NB_AGG = (NN * 32 + 255) / 256;  // warp per node, 8 warps/block
    const int NB_MLP = (NN + 63) / 64;       // 1563
    const int NB_BN = (NN * 16 + 255) / 256; // 6250

    k_init<<<NB_N, 256>>>();
    k_hist<<<NB_E, 256>>>(ei);
    k_bounds<<<NB_N, 256>>>(batch);
    k_scan<<<1, 1024>>>();
    k_scatter<<<NB_E, 256>>>(ei);

    struct Layer {
        const float *wa, *ba, *wb, *bb, *eps, *g, *be;
    } layers[4] = {
        {w1a, b1a, w1b, b1b, eps1, g1, be1},
        {w2a, b2a, w2b, b2b, eps2, g2, be2},
        {w3a, b3a, w3b, b3b, eps3, g3, be3},
        {w3a, b3a, w3b, b3b, eps4, g4, be4},  // conv4 reuses nn3 weights
    };

    for (int l = 0; l < 4; l++) {
        k_agg<<<NB_AGG, 256>>>((const float4*)x, (l == 0) ? 1 : 0, layers[l].eps);
        k_zerobn<<<1, 128>>>();
        k_mlp<<<NB_MLP, 256>>>(layers[l].wa, layers[l].ba, layers[l].wb, layers[l].bb);
        k_bnapply<<<NB_BN, 256>>>(layers[l].g, layers[l].be);
    }

    k_pool<<<GG, 64>>>(wfc, bfc, out);
}

// round 8
// speedup vs baseline: 1.2195x; 1.2176x over previous
#include <cuda_runtime.h>
#include <cuda_bf16.h>

#define NN 100000
#define EE 3200000
#define GG 512
#define NBLK 391   // (NN+255)/256

// ---------------- scratch (device globals; no allocations) ----------------
__device__ float4 g_bufT4[NN * 16];   // agg output t (affine-folded)
__device__ float4 g_bufA4[NN * 16];   // MLP output (pre-BN)
__device__ int    g_deg[NN];
__device__ int    g_rowptr[NN + 1];
__device__ int    g_cursor[NN];
__device__ int    g_col[EE];
__device__ int    g_gs[GG];
__device__ int    g_ge[GG];
__device__ float  g_bn[128];          // [0:64) sum, [64:128) sumsq
__device__ float  g_sc[64];           // BN folded scale
__device__ float  g_sh[64];           // BN folded shift
__device__ int    g_bsum[512];
__device__ int    g_boff[512];

// ---------------- f32x2 helpers ----------------
__device__ __forceinline__ unsigned long long pk2(float lo, float hi) {
    unsigned long long r;
    asm("mov.b64 %0,{%1,%2};" : "=l"(r) : "f"(lo), "f"(hi));
    return r;
}
__device__ __forceinline__ unsigned long long ffma2(unsigned long long a,
                                                    unsigned long long b,
                                                    unsigned long long c) {
    unsigned long long d;
    asm("fma.rn.f32x2 %0,%1,%2,%3;" : "=l"(d) : "l"(a), "l"(b), "l"(c));
    return d;
}
__device__ __forceinline__ void upk2(unsigned long long v, float& lo, float& hi) {
    asm("mov.b64 {%0,%1},%2;" : "=f"(lo), "=f"(hi) : "l"(v));
}

// ---------------- init ----------------
__global__ void k_init() {
    int i = blockIdx.x * blockDim.x + threadIdx.x;
    if (i < NN) g_deg[i] = 0;
    if (i < GG) { g_gs[i] = -1; g_ge[i] = -1; }
    if (i < 128) g_bn[i] = 0.f;
}

// ---------------- CSR build ----------------
__global__ void k_hist(const int* __restrict__ ei) {
    int e = blockIdx.x * blockDim.x + threadIdx.x;
    if (e < EE) atomicAdd(&g_deg[ei[EE + e]], 1);
}

__global__ void k_bounds(const int* __restrict__ batch) {
    int i = blockIdx.x * blockDim.x + threadIdx.x;
    if (i >= NN) return;
    int b = batch[i];
    if (i == 0 || batch[i - 1] != b) g_gs[b] = i;
    if (i == NN - 1 || batch[i + 1] != b) g_ge[b] = i;
}

// multi-block scan: stage 1 — per-block reductions
__global__ void k_blocksum() {
    __shared__ int s[256];
    int t = threadIdx.x;
    int i = blockIdx.x * 256 + t;
    s[t] = (i < NN) ? g_deg[i] : 0;
    __syncthreads();
#pragma unroll
    for (int off = 128; off > 0; off >>= 1) {
        if (t < off) s[t] += s[t + off];
        __syncthreads();
    }
    if (t == 0) g_bsum[blockIdx.x] = s[0];
}

// stage 2 — scan 391 block sums in one block
__global__ void k_scanb() {
    __shared__ int s[512];
    int t = threadIdx.x;
    int v = (t < NBLK) ? g_bsum[t] : 0;
    s[t] = v;
    __syncthreads();
    for (int off = 1; off < 512; off <<= 1) {
        int u = (t >= off) ? s[t - off] : 0;
        __syncthreads();
        s[t] += u;
        __syncthreads();
    }
    if (t < NBLK) g_boff[t] = s[t] - v;  // exclusive
}

// stage 3 — per-block local scan + offset, write rowptr & cursor
__global__ void k_scan2() {
    __shared__ int s[256];
    int t = threadIdx.x;
    int i = blockIdx.x * 256 + t;
    int v = (i < NN) ? g_deg[i] : 0;
    s[t] = v;
    __syncthreads();
    for (int off = 1; off < 256; off <<= 1) {
        int u = (t >= off) ? s[t - off] : 0;
        __syncthreads();
        s[t] += u;
        __syncthreads();
    }
    int base = g_boff[blockIdx.x];
    int ex = base + s[t] - v;
    if (i < NN) { g_rowptr[i] = ex; g_cursor[i] = ex; }
    if (i == NN - 1) g_rowptr[NN] = base + s[t];
}

__global__ void k_scatter(const int* __restrict__ ei) {
    int e = blockIdx.x * blockDim.x + threadIdx.x;
    if (e >= EE) return;
    int s = ei[e];
    int d = ei[EE + e];
    int p = atomicAdd(&g_cursor[d], 1);
    g_col[p] = s;
}

// ---------------- aggregation with folded BN affine ----------------
// raw = (1+eps)*a[i] + sum_{j} a[j];  t = sc*raw + (1+eps+deg)*sh
// one warp per node; two half-warps, each with 2-deep ILP gather
__global__ void k_agg(const float4* __restrict__ xext, int use_ext,
                      const float* __restrict__ epsp) {
    int warp = (blockIdx.x * blockDim.x + threadIdx.x) >> 5;
    if (warp >= NN) return;
    const float4* __restrict__ x = use_ext ? xext : g_bufA4;
    int lane = threadIdx.x & 31;
    int half = lane >> 4;
    int li = lane & 15;
    float e1 = 1.0f + *epsp;

    float4 acc = make_float4(0.f, 0.f, 0.f, 0.f);
    float4 accB = make_float4(0.f, 0.f, 0.f, 0.f);
    if (half == 0) {
        float4 v = x[warp * 16 + li];
        acc.x = e1 * v.x; acc.y = e1 * v.y; acc.z = e1 * v.z; acc.w = e1 * v.w;
    }
    int s = g_rowptr[warp], e = g_rowptr[warp + 1];
    int j = s + half;
    // 2-way ILP: process neighbors j and j+2 together
    for (; j + 2 < e; j += 4) {
        int s0 = __ldg(&g_col[j]);
        int s1 = __ldg(&g_col[j + 2]);
        float4 v0 = x[s0 * 16 + li];
        float4 v1 = x[s1 * 16 + li];
        acc.x += v0.x; acc.y += v0.y; acc.z += v0.z; acc.w += v0.w;
        accB.x += v1.x; accB.y += v1.y; accB.z += v1.z; accB.w += v1.w;
    }
    for (; j < e; j += 2) {
        int src = __ldg(&g_col[j]);
        float4 v = x[src * 16 + li];
        acc.x += v.x; acc.y += v.y; acc.z += v.z; acc.w += v.w;
    }
    acc.x += accB.x; acc.y += accB.y; acc.z += accB.z; acc.w += accB.w;

    acc.x += __shfl_xor_sync(0xffffffff, acc.x, 16);
    acc.y += __shfl_xor_sync(0xffffffff, acc.y, 16);
    acc.z += __shfl_xor_sync(0xffffffff, acc.z, 16);
    acc.w += __shfl_xor_sync(0xffffffff, acc.w, 16);

    if (half == 0) {
        if (!use_ext) {
            float4 sc = *(const float4*)&g_sc[li * 4];
            float4 sh = *(const float4*)&g_sh[li * 4];
            float coef = e1 + (float)(e - s);
            acc.x = fmaf(acc.x, sc.x, coef * sh.x);
            acc.y = fmaf(acc.y, sc.y, coef * sh.y);
            acc.z = fmaf(acc.z, sc.z, coef * sh.z);
            acc.w = fmaf(acc.w, sc.w, coef * sh.w);
        }
        g_bufT4[warp * 16 + li] = acc;
    }
}

// ---------------- BN stats -> folded affine, re-zero accumulators ----------------
__global__ void k_bnstats(const float* __restrict__ gam, const float* __restrict__ bet) {
    int c = threadIdx.x;  // 64 threads
    float inv = 1.0f / (float)NN;
    float mu = g_bn[c] * inv;
    float var = g_bn[64 + c] * inv - mu * mu;
    float s = gam[c] * rsqrtf(var + 1e-5f);
    g_sc[c] = s;
    g_sh[c] = bet[c] - mu * s;
    g_bn[c] = 0.f;
    g_bn[64 + c] = 0.f;
}

// ---------------- fused MLP (f32x2 packed FMA) + BN partial sums ----------------
__global__ __launch_bounds__(256) void k_mlp(const float* __restrict__ wa,
                                             const float* __restrict__ ba,
                                             const float* __restrict__ wb,
                                             const float* __restrict__ bb) {
    __shared__ float sT[64][68];     // transposed tile sT[k][node]
    __shared__ float sW[64 * 64];    // weights (wa then wb); 256B rows, 16B aligned
    __shared__ float sB[64];
    __shared__ float sRed[16][128];

    const float* __restrict__ tin = (const float*)g_bufT4;
    float* __restrict__ out = (float*)g_bufA4;

    int tid = threadIdx.x;
    int n0 = blockIdx.x * 64;

    for (int idx = tid; idx < 64 * 64; idx += 256) {
        int r = idx >> 6, k = idx & 63;
        int node = n0 + r;
        float v = (node < NN) ? tin[node * 64 + k] : 0.f;
        sT[k][r] = v;
    }
    for (int idx = tid; idx < 4096; idx += 256) sW[idx] = wa[idx];
    if (tid < 64) sB[tid] = ba[tid];
    __syncthreads();

    int tx = tid & 15;   // channel quad
    int ty = tid >> 4;   // node quad

    unsigned long long accP[4][2];
#pragma unroll
    for (int i = 0; i < 4; i++) { accP[i][0] = 0ULL; accP[i][1] = 0ULL; }

#pragma unroll 16
    for (int k = 0; k < 64; k++) {
        float4 a = *(const float4*)&sT[k][ty * 4];
        ulonglong2 b2 = *(const ulonglong2*)(sW + k * 64 + tx * 4);
        float av[4] = {a.x, a.y, a.z, a.w};
#pragma unroll
        for (int i = 0; i < 4; i++) {
            unsigned long long aa = pk2(av[i], av[i]);
            accP[i][0] = ffma2(aa, b2.x, accP[i][0]);
            accP[i][1] = ffma2(aa, b2.y, accP[i][1]);
        }
    }
    __syncthreads();  // all reads of sT/sW done

    // mid = relu(acc + ba), stored transposed back into sT
    {
        float m[4][4];
#pragma unroll
        for (int i = 0; i < 4; i++) {
            upk2(accP[i][0], m[i][0], m[i][1]);
            upk2(accP[i][1], m[i][2], m[i][3]);
        }
#pragma unroll
        for (int j = 0; j < 4; j++) {
            float bias = sB[4 * tx + j];
            float4 w;
            w.x = fmaxf(m[0][j] + bias, 0.f);
            w.y = fmaxf(m[1][j] + bias, 0.f);
            w.z = fmaxf(m[2][j] + bias, 0.f);
            w.w = fmaxf(m[3][j] + bias, 0.f);
            *(float4*)&sT[4 * tx + j][4 * ty] = w;
        }
    }
    for (int idx = tid; idx < 4096; idx += 256) sW[idx] = wb[idx];
    if (tid < 64) sB[tid] = bb[tid];
    __syncthreads();

#pragma unroll
    for (int i = 0; i < 4; i++) { accP[i][0] = 0ULL; accP[i][1] = 0ULL; }

#pragma unroll 16
    for (int k = 0; k < 64; k++) {
        float4 a = *(const float4*)&sT[k][ty * 4];
        ulonglong2 b2 = *(const ulonglong2*)(sW + k * 64 + tx * 4);
        float av[4] = {a.x, a.y, a.z, a.w};
#pragma unroll
        for (int i = 0; i < 4; i++) {
            unsigned long long aa = pk2(av[i], av[i]);
            accP[i][0] = ffma2(aa, b2.x, accP[i][0]);
            accP[i][1] = ffma2(aa, b2.y, accP[i][1]);
        }
    }

    // out = relu(acc2 + bb), write + BN partials
    float m2[4][4];
#pragma unroll
    for (int i = 0; i < 4; i++) {
        upk2(accP[i][0], m2[i][0], m2[i][1]);
        upk2(accP[i][1], m2[i][2], m2[i][3]);
    }
    float psum[4] = {0.f, 0.f, 0.f, 0.f};
    float psq[4] = {0.f, 0.f, 0.f, 0.f};
#pragma unroll
    for (int i = 0; i < 4; i++) {
        int node = n0 + 4 * ty + i;
        float o[4];
#pragma unroll
        for (int j = 0; j < 4; j++) o[j] = fmaxf(m2[i][j] + sB[4 * tx + j], 0.f);
        if (node < NN) {
            float4 ov = make_float4(o[0], o[1], o[2], o[3]);
            *(float4*)&out[node * 64 + 4 * tx] = ov;
#pragma unroll
            for (int j = 0; j < 4; j++) {
                psum[j] += o[j];
                psq[j] = fmaf(o[j], o[j], psq[j]);
            }
        }
    }
#pragma unroll
    for (int j = 0; j < 4; j++) {
        sRed[ty][4 * tx + j] = psum[j];
        sRed[ty][64 + 4 * tx + j] = psq[j];
    }
    __syncthreads();
    if (tid < 128) {
        float s = 0.f;
#pragma unroll
        for (int r = 0; r < 16; r++) s += sRed[r][tid];
        atomicAdd(&g_bn[tid], s);
    }
}

// ---------------- fused pooling (mean+max, BN folded) + FC + log_softmax ----------------
__global__ void k_pool(const float* __restrict__ wfc, const float* __restrict__ bfc,
                       float* __restrict__ outp) {
    int g = blockIdx.x;
    int tid = threadIdx.x;  // 256 threads
    int r = tid >> 6;       // 0..3
    int c = tid & 63;
    __shared__ float ssum[4][64], smax[4][64], smin[4][64];
    __shared__ float sm[128];
    __shared__ float sz[6];
    const float* __restrict__ h = (const float*)g_bufA4;

    int s = g_gs[g], e = g_ge[g];
    float sum = 0.f, mx = -3.4e38f, mn = 3.4e38f;
    if (s >= 0) {
        for (int i = s + r; i <= e; i += 4) {
            float v = h[i * 64 + c];
            sum += v;
            mx = fmaxf(mx, v);
            mn = fminf(mn, v);
        }
    }
    ssum[r][c] = sum; smax[r][c] = mx; smin[r][c] = mn;
    __syncthreads();
    if (r == 0) {
        if (s >= 0) {
            float S = ssum[0][c] + ssum[1][c] + ssum[2][c] + ssum[3][c];
            float MX = fmaxf(fmaxf(smax[0][c], smax[1][c]), fmaxf(smax[2][c], smax[3][c]));
            float MN = fminf(fminf(smin[0][c], smin[1][c]), fminf(smin[2][c], smin[3][c]));
            float cnt = (float)(e - s + 1);
            float sc = g_sc[c], sh = g_sh[c];
            sm[c] = fmaf(sc, S / cnt, sh);
            sm[64 + c] = (sc >= 0.f) ? fmaf(sc, MX, sh) : fmaf(sc, MN, sh);
        } else {
            sm[c] = 0.f;
            sm[64 + c] = 0.f;
        }
    }
    __syncthreads();
    if (tid < 6) {
        float z = bfc[tid];
#pragma unroll 8
        for (int k = 0; k < 128; k++) z = fmaf(sm[k], wfc[k * 6 + tid], z);
        sz[tid] = z;
    }
    __syncthreads();
    if (tid == 0) {
        float m = sz[0];
#pragma unroll
        for (int j = 1; j < 6; j++) m = fmaxf(m, sz[j]);
        float se = 0.f;
#pragma unroll
        for (int j = 0; j < 6; j++) se += expf(sz[j] - m);
        float lse = m + logf(se);
#pragma unroll
        for (int j = 0; j < 6; j++) outp[g * 6 + j] = sz[j] - lse;
    }
}

// ---------------- launch ----------------
extern "C" void kernel_launch(void* const* d_in, const int* in_sizes, int n_in,
                              void* d_out, int out_size) {
    const float* x = (const float*)d_in[0];
    const int* ei = (const int*)d_in[1];
    const int* batch = (const int*)d_in[2];
    const float* w1a = (const float*)d_in[3];
    const float* b1a = (const float*)d_in[4];
    const float* w1b = (const float*)d_in[5];
    const float* b1b = (const float*)d_in[6];
    const float* w2a = (const float*)d_in[7];
    const float* b2a = (const float*)d_in[8];
    const float* w2b = (const float*)d_in[9];
    const float* b2b = (const float*)d_in[10];
    const float* w3a = (const float*)d_in[11];
    const float* b3a = (const float*)d_in[12];
    const float* w3b = (const float*)d_in[13];
    const float* b3b = (const float*)d_in[14];
    const float* eps1 = (const float*)d_in[15];
    const float* g1 = (const float*)d_in[16];
    const float* be1 = (const float*)d_in[17];
    const float* eps2 = (const float*)d_in[18];
    const float* g2 = (const float*)d_in[19];
    const float* be2 = (const float*)d_in[20];
    const float* eps3 = (const float*)d_in[21];
    const float* g3 = (const float*)d_in[22];
    const float* be3 = (const float*)d_in[23];
    const float* eps4 = (const float*)d_in[24];
    const float* g4 = (const float*)d_in[25];
    const float* be4 = (const float*)d_in[26];
    const float* wfc = (const float*)d_in[27];
    const float* bfc = (const float*)d_in[28];
    float* out = (float*)d_out;

    const int NB_N = NBLK;                      // 391
    const int NB_E = (EE + 255) / 256;          // 12500
    const int NB_AGG = (NN * 32 + 255) / 256;   // warp per node
    const int NB_MLP = (NN + 63) / 64;          // 1563

    k_init<<<NB_N, 256>>>();
    k_hist<<<NB_E, 256>>>(ei);
    k_bounds<<<NB_N, 256>>>(batch);
    k_blocksum<<<NB_N, 256>>>();
    k_scanb<<<1, 512>>>();
    k_scan2<<<NB_N, 256>>>();
    k_scatter<<<NB_E, 256>>>(ei);

    struct Layer {
        const float *wa, *ba, *wb, *bb, *eps, *g, *be;
    } layers[4] = {
        {w1a, b1a, w1b, b1b, eps1, g1, be1},
        {w2a, b2a, w2b, b2b, eps2, g2, be2},
        {w3a, b3a, w3b, b3b, eps3, g3, be3},
        {w3a, b3a, w3b, b3b, eps4, g4, be4},  // conv4 reuses nn3 weights
    };

    for (int l = 0; l < 4; l++) {
        k_agg<<<NB_AGG, 256>>>((const float4*)x, (l == 0) ? 1 : 0, layers[l].eps);
        k_mlp<<<NB_MLP, 256>>>(layers[l].wa, layers[l].ba, layers[l].wb, layers[l].bb);
        k_bnstats<<<1, 64>>>(layers[l].g, layers[l].be);
    }

    k_pool<<<GG, 256>>>(wfc, bfc, out);
}

// round 9
// speedup vs baseline: 1.4015x; 1.1492x over previous
#include <cuda_runtime.h>
#include <cuda_fp16.h>
#include <cuda_bf16.h>

#define NN 100000
#define EE 3200000
#define GG 512
#define NBLK 391   // (NN+255)/256

// ---------------- scratch (device globals; no allocations) ----------------
__device__ float4 g_bufT4[NN * 16];   // agg output t (affine-folded), fp32
__device__ float4 g_bufA4[NN * 16];   // layer-4 MLP output (for pooling), fp32
__device__ uint2  g_bufH[NN * 16];    // fp16 feature table (gather source), 128B rows
__device__ int    g_deg[NN];
__device__ int    g_rowptr[NN + 1];
__device__ int    g_cursor[NN];
__device__ int    g_col[EE];
__device__ int    g_gs[GG];
__device__ int    g_ge[GG];
__device__ float  g_bn[128];          // [0:64) sum, [64:128) sumsq
__device__ float  g_sc[64];           // BN folded scale
__device__ float  g_sh[64];           // BN folded shift
__device__ int    g_bsum[512];
__device__ int    g_boff[512];

// ---------------- f32x2 helpers ----------------
__device__ __forceinline__ unsigned long long pk2(float lo, float hi) {
    unsigned long long r;
    asm("mov.b64 %0,{%1,%2};" : "=l"(r) : "f"(lo), "f"(hi));
    return r;
}
__device__ __forceinline__ unsigned long long ffma2(unsigned long long a,
                                                    unsigned long long b,
                                                    unsigned long long c) {
    unsigned long long d;
    asm("fma.rn.f32x2 %0,%1,%2,%3;" : "=l"(d) : "l"(a), "l"(b), "l"(c));
    return d;
}
__device__ __forceinline__ void upk2(unsigned long long v, float& lo, float& hi) {
    asm("mov.b64 {%0,%1},%2;" : "=f"(lo), "=f"(hi) : "l"(v));
}

// ---------------- init ----------------
__global__ void k_init() {
    int i = blockIdx.x * blockDim.x + threadIdx.x;
    if (i < NN) g_deg[i] = 0;
    if (i < GG) { g_gs[i] = -1; g_ge[i] = -1; }
    if (i < 128) g_bn[i] = 0.f;
}

// ---------------- x -> fp16 table ----------------
__global__ void k_toh(const float2* __restrict__ x2) {
    int i = blockIdx.x * blockDim.x + threadIdx.x;  // half2 index, NN*32 total
    if (i < NN * 32) {
        float2 v = x2[i];
        ((__half2*)g_bufH)[i] = __floats2half2_rn(v.x, v.y);
    }
}

// ---------------- CSR build ----------------
__global__ void k_hist(const int* __restrict__ ei) {
    int e = blockIdx.x * blockDim.x + threadIdx.x;
    if (e < EE) atomicAdd(&g_deg[ei[EE + e]], 1);
}

__global__ void k_bounds(const int* __restrict__ batch) {
    int i = blockIdx.x * blockDim.x + threadIdx.x;
    if (i >= NN) return;
    int b = batch[i];
    if (i == 0 || batch[i - 1] != b) g_gs[b] = i;
    if (i == NN - 1 || batch[i + 1] != b) g_ge[b] = i;
}

__global__ void k_blocksum() {
    __shared__ int s[256];
    int t = threadIdx.x;
    int i = blockIdx.x * 256 + t;
    s[t] = (i < NN) ? g_deg[i] : 0;
    __syncthreads();
#pragma unroll
    for (int off = 128; off > 0; off >>= 1) {
        if (t < off) s[t] += s[t + off];
        __syncthreads();
    }
    if (t == 0) g_bsum[blockIdx.x] = s[0];
}

__global__ void k_scanb() {
    __shared__ int s[512];
    int t = threadIdx.x;
    int v = (t < NBLK) ? g_bsum[t] : 0;
    s[t] = v;
    __syncthreads();
    for (int off = 1; off < 512; off <<= 1) {
        int u = (t >= off) ? s[t - off] : 0;
        __syncthreads();
        s[t] += u;
        __syncthreads();
    }
    if (t < NBLK) g_boff[t] = s[t] - v;  // exclusive
}

__global__ void k_scan2() {
    __shared__ int s[256];
    int t = threadIdx.x;
    int i = blockIdx.x * 256 + t;
    int v = (i < NN) ? g_deg[i] : 0;
    s[t] = v;
    __syncthreads();
    for (int off = 1; off < 256; off <<= 1) {
        int u = (t >= off) ? s[t - off] : 0;
        __syncthreads();
        s[t] += u;
        __syncthreads();
    }
    int base = g_boff[blockIdx.x];
    int ex = base + s[t] - v;
    if (i < NN) { g_rowptr[i] = ex; g_cursor[i] = ex; }
    if (i == NN - 1) g_rowptr[NN] = base + s[t];
}

__global__ void k_scatter(const int* __restrict__ ei) {
    int e = blockIdx.x * blockDim.x + threadIdx.x;
    if (e >= EE) return;
    int s = ei[e];
    int d = ei[EE + e];
    int p = atomicAdd(&g_cursor[d], 1);
    g_col[p] = s;
}

// ---------------- aggregation over fp16 table, fp32 accumulate ----------------
// half-warp (16 lanes) per node; each lane owns 4 channels (one uint2 = 4 halves).
// raw = (1+eps)*a[i] + sum_j a[j];  if fold: t = sc*raw + (1+eps+deg)*sh
__global__ void k_agg_h(const float* __restrict__ epsp, int fold) {
    int node = (blockIdx.x * blockDim.x + threadIdx.x) >> 4;
    if (node >= NN) return;
    int li = threadIdx.x & 15;
    const uint2* __restrict__ H = g_bufH;
    float e1 = 1.0f + *epsp;

    // self term
    uint2 sv = H[node * 16 + li];
    float2 s0 = __half22float2(*(const __half2*)&sv.x);
    float2 s1 = __half22float2(*(const __half2*)&sv.y);
    float4 a0 = make_float4(e1 * s0.x, e1 * s0.y, e1 * s1.x, e1 * s1.y);
    float4 a1 = make_float4(0.f, 0.f, 0.f, 0.f);

    int s = g_rowptr[node], e = g_rowptr[node + 1];
    int j = s;
    for (; j + 1 < e; j += 2) {
        int n0 = __ldg(&g_col[j]);
        int n1 = __ldg(&g_col[j + 1]);
        uint2 v0 = H[n0 * 16 + li];
        uint2 v1 = H[n1 * 16 + li];
        float2 p0 = __half22float2(*(const __half2*)&v0.x);
        float2 p1 = __half22float2(*(const __half2*)&v0.y);
        float2 q0 = __half22float2(*(const __half2*)&v1.x);
        float2 q1 = __half22float2(*(const __half2*)&v1.y);
        a0.x += p0.x; a0.y += p0.y; a0.z += p1.x; a0.w += p1.y;
        a1.x += q0.x; a1.y += q0.y; a1.z += q1.x; a1.w += q1.y;
    }
    if (j < e) {
        int n0 = __ldg(&g_col[j]);
        uint2 v0 = H[n0 * 16 + li];
        float2 p0 = __half22float2(*(const __half2*)&v0.x);
        float2 p1 = __half22float2(*(const __half2*)&v0.y);
        a0.x += p0.x; a0.y += p0.y; a0.z += p1.x; a0.w += p1.y;
    }
    a0.x += a1.x; a0.y += a1.y; a0.z += a1.z; a0.w += a1.w;

    if (fold) {
        float4 sc = *(const float4*)&g_sc[li * 4];
        float4 sh = *(const float4*)&g_sh[li * 4];
        float coef = e1 + (float)(e - s);
        a0.x = fmaf(a0.x, sc.x, coef * sh.x);
        a0.y = fmaf(a0.y, sc.y, coef * sh.y);
        a0.z = fmaf(a0.z, sc.z, coef * sh.z);
        a0.w = fmaf(a0.w, sc.w, coef * sh.w);
    }
    g_bufT4[node * 16 + li] = a0;
}

// ---------------- BN stats -> folded affine, re-zero accumulators ----------------
__global__ void k_bnstats(const float* __restrict__ gam, const float* __restrict__ bet) {
    int c = threadIdx.x;  // 64 threads
    float inv = 1.0f / (float)NN;
    float mu = g_bn[c] * inv;
    float var = g_bn[64 + c] * inv - mu * mu;
    float s = gam[c] * rsqrtf(var + 1e-5f);
    g_sc[c] = s;
    g_sh[c] = bet[c] - mu * s;
    g_bn[c] = 0.f;
    g_bn[64 + c] = 0.f;
}

// ---------------- fused MLP (f32x2 packed FMA) + BN partial sums ----------------
// writes fp16 table always; fp32 buffer only when wfp32 (layer 4, for pooling)
__global__ __launch_bounds__(256) void k_mlp(const float* __restrict__ wa,
                                             const float* __restrict__ ba,
                                             const float* __restrict__ wb,
                                             const float* __restrict__ bb,
                                             int wfp32) {
    __shared__ float sT[64][68];     // transposed tile sT[k][node]
    __shared__ float sW[64 * 64];
    __shared__ float sB[64];
    __shared__ float sRed[16][128];

    const float* __restrict__ tin = (const float*)g_bufT4;
    float* __restrict__ out = (float*)g_bufA4;

    int tid = threadIdx.x;
    int n0 = blockIdx.x * 64;

    for (int idx = tid; idx < 64 * 64; idx += 256) {
        int r = idx >> 6, k = idx & 63;
        int node = n0 + r;
        float v = (node < NN) ? tin[node * 64 + k] : 0.f;
        sT[k][r] = v;
    }
    for (int idx = tid; idx < 4096; idx += 256) sW[idx] = wa[idx];
    if (tid < 64) sB[tid] = ba[tid];
    __syncthreads();

    int tx = tid & 15;   // channel quad
    int ty = tid >> 4;   // node quad

    unsigned long long accP[4][2];
#pragma unroll
    for (int i = 0; i < 4; i++) { accP[i][0] = 0ULL; accP[i][1] = 0ULL; }

#pragma unroll 16
    for (int k = 0; k < 64; k++) {
        float4 a = *(const float4*)&sT[k][ty * 4];
        ulonglong2 b2 = *(const ulonglong2*)(sW + k * 64 + tx * 4);
        float av[4] = {a.x, a.y, a.z, a.w};
#pragma unroll
        for (int i = 0; i < 4; i++) {
            unsigned long long aa = pk2(av[i], av[i]);
            accP[i][0] = ffma2(aa, b2.x, accP[i][0]);
            accP[i][1] = ffma2(aa, b2.y, accP[i][1]);
        }
    }
    __syncthreads();  // all reads of sT/sW done

    // mid = relu(acc + ba), stored transposed back into sT
    {
        float m[4][4];
#pragma unroll
        for (int i = 0; i < 4; i++) {
            upk2(accP[i][0], m[i][0], m[i][1]);
            upk2(accP[i][1], m[i][2], m[i][3]);
        }
#pragma unroll
        for (int j = 0; j < 4; j++) {
            float bias = sB[4 * tx + j];
            float4 w;
            w.x = fmaxf(m[0][j] + bias, 0.f);
            w.y = fmaxf(m[1][j] + bias, 0.f);
            w.z = fmaxf(m[2][j] + bias, 0.f);
            w.w = fmaxf(m[3][j] + bias, 0.f);
            *(float4*)&sT[4 * tx + j][4 * ty] = w;
        }
    }
    for (int idx = tid; idx < 4096; idx += 256) sW[idx] = wb[idx];
    if (tid < 64) sB[tid] = bb[tid];
    __syncthreads();

#pragma unroll
    for (int i = 0; i < 4; i++) { accP[i][0] = 0ULL; accP[i][1] = 0ULL; }

#pragma unroll 16
    for (int k = 0; k < 64; k++) {
        float4 a = *(const float4*)&sT[k][ty * 4];
        ulonglong2 b2 = *(const ulonglong2*)(sW + k * 64 + tx * 4);
        float av[4] = {a.x, a.y, a.z, a.w};
#pragma unroll
        for (int i = 0; i < 4; i++) {
            unsigned long long aa = pk2(av[i], av[i]);
            accP[i][0] = ffma2(aa, b2.x, accP[i][0]);
            accP[i][1] = ffma2(aa, b2.y, accP[i][1]);
        }
    }

    // out = relu(acc2 + bb): fp16 table write + optional fp32 write + BN partials
    float m2[4][4];
#pragma unroll
    for (int i = 0; i < 4; i++) {
        upk2(accP[i][0], m2[i][0], m2[i][1]);
        upk2(accP[i][1], m2[i][2], m2[i][3]);
    }
    float psum[4] = {0.f, 0.f, 0.f, 0.f};
    float psq[4] = {0.f, 0.f, 0.f, 0.f};
#pragma unroll
    for (int i = 0; i < 4; i++) {
        int node = n0 + 4 * ty + i;
        float o[4];
#pragma unroll
        for (int j = 0; j < 4; j++) o[j] = fmaxf(m2[i][j] + sB[4 * tx + j], 0.f);
        if (node < NN) {
            __half2 h0 = __floats2half2_rn(o[0], o[1]);
            __half2 h1 = __floats2half2_rn(o[2], o[3]);
            uint2 hv;
            hv.x = *(const unsigned int*)&h0;
            hv.y = *(const unsigned int*)&h1;
            g_bufH[node * 16 + tx] = hv;
            if (wfp32) {
                float4 ov = make_float4(o[0], o[1], o[2], o[3]);
                *(float4*)&out[node * 64 + 4 * tx] = ov;
            }
#pragma unroll
            for (int j = 0; j < 4; j++) {
                psum[j] += o[j];
                psq[j] = fmaf(o[j], o[j], psq[j]);
            }
        }
    }
#pragma unroll
    for (int j = 0; j < 4; j++) {
        sRed[ty][4 * tx + j] = psum[j];
        sRed[ty][64 + 4 * tx + j] = psq[j];
    }
    __syncthreads();
    if (tid < 128) {
        float s = 0.f;
#pragma unroll
        for (int r = 0; r < 16; r++) s += sRed[r][tid];
        atomicAdd(&g_bn[tid], s);
    }
}

// ---------------- fused pooling (mean+max, BN folded) + FC + log_softmax ----------------
__global__ void k_pool(const float* __restrict__ wfc, const float* __restrict__ bfc,
                       float* __restrict__ outp) {
    int g = blockIdx.x;
    int tid = threadIdx.x;  // 256 threads
    int r = tid >> 6;       // 0..3
    int c = tid & 63;
    __shared__ float ssum[4][64], smax[4][64], smin[4][64];
    __shared__ float sm[128];
    __shared__ float sz[6];
    const float* __restrict__ h = (const float*)g_bufA4;

    int s = g_gs[g], e = g_ge[g];
    float sum = 0.f, mx = -3.4e38f, mn = 3.4e38f;
    if (s >= 0) {
        for (int i = s + r; i <= e; i += 4) {
            float v = h[i * 64 + c];
            sum += v;
            mx = fmaxf(mx, v);
            mn = fminf(mn, v);
        }
    }
    ssum[r][c] = sum; smax[r][c] = mx; smin[r][c] = mn;
    __syncthreads();
    if (r == 0) {
        if (s >= 0) {
            float S = ssum[0][c] + ssum[1][c] + ssum[2][c] + ssum[3][c];
            float MX = fmaxf(fmaxf(smax[0][c], smax[1][c]), fmaxf(smax[2][c], smax[3][c]));
            float MN = fminf(fminf(smin[0][c], smin[1][c]), fminf(smin[2][c], smin[3][c]));
            float cnt = (float)(e - s + 1);
            float sc = g_sc[c], sh = g_sh[c];
            sm[c] = fmaf(sc, S / cnt, sh);
            sm[64 + c] = (sc >= 0.f) ? fmaf(sc, MX, sh) : fmaf(sc, MN, sh);
        } else {
            sm[c] = 0.f;
            sm[64 + c] = 0.f;
        }
    }
    __syncthreads();
    if (tid < 6) {
        float z = bfc[tid];
#pragma unroll 8
        for (int k = 0; k < 128; k++) z = fmaf(sm[k], wfc[k * 6 + tid], z);
        sz[tid] = z;
    }
    __syncthreads();
    if (tid == 0) {
        float m = sz[0];
#pragma unroll
        for (int j = 1; j < 6; j++) m = fmaxf(m, sz[j]);
        float se = 0.f;
#pragma unroll
        for (int j = 0; j < 6; j++) se += expf(sz[j] - m);
        float lse = m + logf(se);
#pragma unroll
        for (int j = 0; j < 6; j++) outp[g * 6 + j] = sz[j] - lse;
    }
}

// ---------------- launch ----------------
extern "C" void kernel_launch(void* const* d_in, const int* in_sizes, int n_in,
                              void* d_out, int out_size) {
    const float* x = (const float*)d_in[0];
    const int* ei = (const int*)d_in[1];
    const int* batch = (const int*)d_in[2];
    const float* w1a = (const float*)d_in[3];
    const float* b1a = (const float*)d_in[4];
    const float* w1b = (const float*)d_in[5];
    const float* b1b = (const float*)d_in[6];
    const float* w2a = (const float*)d_in[7];
    const float* b2a = (const float*)d_in[8];
    const float* w2b = (const float*)d_in[9];
    const float* b2b = (const float*)d_in[10];
    const float* w3a = (const float*)d_in[11];
    const float* b3a = (const float*)d_in[12];
    const float* w3b = (const float*)d_in[13];
    const float* b3b = (const float*)d_in[14];
    const float* eps1 = (const float*)d_in[15];
    const float* g1 = (const float*)d_in[16];
    const float* be1 = (const float*)d_in[17];
    const float* eps2 = (const float*)d_in[18];
    const float* g2 = (const float*)d_in[19];
    const float* be2 = (const float*)d_in[20];
    const float* eps3 = (const float*)d_in[21];
    const float* g3 = (const float*)d_in[22];
    const float* be3 = (const float*)d_in[23];
    const float* eps4 = (const float*)d_in[24];
    const float* g4 = (const float*)d_in[25];
    const float* be4 = (const float*)d_in[26];
    const float* wfc = (const float*)d_in[27];
    const float* bfc = (const float*)d_in[28];
    float* out = (float*)d_out;

    const int NB_N = NBLK;                       // 391
    const int NB_E = (EE + 255) / 256;           // 12500
    const int NB_AGG = (NN * 16 + 255) / 256;    // half-warp per node
    const int NB_MLP = (NN + 63) / 64;           // 1563
    const int NB_TOH = (NN * 32 + 255) / 256;    // 12500

    k_init<<<NB_N, 256>>>();
    k_toh<<<NB_TOH, 256>>>((const float2*)x);
    k_hist<<<NB_E, 256>>>(ei);
    k_bounds<<<NB_N, 256>>>(batch);
    k_blocksum<<<NB_N, 256>>>();
    k_scanb<<<1, 512>>>();
    k_scan2<<<NB_N, 256>>>();
    k_scatter<<<NB_E, 256>>>(ei);

    struct Layer {
        const float *wa, *ba, *wb, *bb, *eps, *g, *be;
    } layers[4] = {
        {w1a, b1a, w1b, b1b, eps1, g1, be1},
        {w2a, b2a, w2b, b2b, eps2, g2, be2},
        {w3a, b3a, w3b, b3b, eps3, g3, be3},
        {w3a, b3a, w3b, b3b, eps4, g4, be4},  // conv4 reuses nn3 weights
    };

    for (int l = 0; l < 4; l++) {
        k_agg_h<<<NB_AGG, 256>>>(layers[l].eps, (l == 0) ? 0 : 1);
        k_mlp<<<NB_MLP, 256>>>(layers[l].wa, layers[l].ba, layers[l].wb, layers[l].bb,
                               (l == 3) ? 1 : 0);
        k_bnstats<<<1, 64>>>(layers[l].g, layers[l].be);
    }

    k_pool<<<GG, 256>>>(wfc, bfc, out);
}

// round 11
// speedup vs baseline: 1.4606x; 1.0422x over previous
#include <cuda_runtime.h>
#include <cuda_fp16.h>
#include <cuda_bf16.h>

#define NN 100000
#define EE 3200000
#define GG 512
#define NBLK 391   // (NN+255)/256

// ---------------- scratch (device globals; no allocations) ----------------
__device__ float4 g_bufA4[NN * 16];   // layer-4 MLP output (for pooling), fp32
__device__ uint2  g_bufH0[NN * 16];   // fp16 feature table, buffer 0 (128B rows)
__device__ uint2  g_bufH1[NN * 16];   // fp16 feature table, buffer 1
__device__ int    g_deg[NN];
__device__ int    g_rowptr[NN + 1];
__device__ int    g_cursor[NN];
__device__ int    g_col[EE];
__device__ int    g_gs[GG];
__device__ int    g_ge[GG];
__device__ float  g_bn[128];          // [0:64) sum, [64:128) sumsq
__device__ float  g_sc[64];           // BN folded scale
__device__ float  g_sh[64];           // BN folded shift
__device__ int    g_bsum[512];
__device__ int    g_boff[512];

// ---------------- f32x2 helpers ----------------
__device__ __forceinline__ unsigned long long pk2(float lo, float hi) {
    unsigned long long r;
    asm("mov.b64 %0,{%1,%2};" : "=l"(r) : "f"(lo), "f"(hi));
    return r;
}
__device__ __forceinline__ unsigned long long ffma2(unsigned long long a,
                                                    unsigned long long b,
                                                    unsigned long long c) {
    unsigned long long d;
    asm("fma.rn.f32x2 %0,%1,%2,%3;" : "=l"(d) : "l"(a), "l"(b), "l"(c));
    return d;
}
__device__ __forceinline__ void upk2(unsigned long long v, float& lo, float& hi) {
    asm("mov.b64 {%0,%1},%2;" : "=f"(lo), "=f"(hi) : "l"(v));
}

// ---------------- init ----------------
__global__ void k_init() {
    int i = blockIdx.x * blockDim.x + threadIdx.x;
    if (i < NN) g_deg[i] = 0;
    if (i < GG) { g_gs[i] = -1; g_ge[i] = -1; }
    if (i < 128) g_bn[i] = 0.f;
}

// ---------------- x -> fp16 table (buffer 0) AND edge histogram (EE == NN*32) --
__global__ void k_toh_hist(const float2* __restrict__ x2, const int* __restrict__ ei) {
    int i = blockIdx.x * blockDim.x + threadIdx.x;
    if (i < NN * 32) {
        float2 v = x2[i];
        ((__half2*)g_bufH0)[i] = __floats2half2_rn(v.x, v.y);
    }
    if (i < EE) atomicAdd(&g_deg[ei[EE + i]], 1);
}

// ---------------- graph bounds + per-block degree sums (both grid NBLK) -------
__global__ void k_bounds_bsum(const int* __restrict__ batch) {
    __shared__ int s[256];
    int t = threadIdx.x;
    int i = blockIdx.x * 256 + t;
    if (i < NN) {
        int b = batch[i];
        if (i == 0 || batch[i - 1] != b) g_gs[b] = i;
        if (i == NN - 1 || batch[i + 1] != b) g_ge[b] = i;
    }
    s[t] = (i < NN) ? g_deg[i] : 0;
    __syncthreads();
#pragma unroll
    for (int off = 128; off > 0; off >>= 1) {
        if (t < off) s[t] += s[t + off];
        __syncthreads();
    }
    if (t == 0) g_bsum[blockIdx.x] = s[0];
}

__global__ void k_scanb() {
    __shared__ int s[512];
    int t = threadIdx.x;
    int v = (t < NBLK) ? g_bsum[t] : 0;
    s[t] = v;
    __syncthreads();
    for (int off = 1; off < 512; off <<= 1) {
        int u = (t >= off) ? s[t - off] : 0;
        __syncthreads();
        s[t] += u;
        __syncthreads();
    }
    if (t < NBLK) g_boff[t] = s[t] - v;  // exclusive
}

__global__ void k_scan2() {
    __shared__ int s[256];
    int t = threadIdx.x;
    int i = blockIdx.x * 256 + t;
    int v = (i < NN) ? g_deg[i] : 0;
    s[t] = v;
    __syncthreads();
    for (int off = 1; off < 256; off <<= 1) {
        int u = (t >= off) ? s[t - off] : 0;
        __syncthreads();
        s[t] += u;
        __syncthreads();
    }
    int base = g_boff[blockIdx.x];
    int ex = base + s[t] - v;
    if (i < NN) { g_rowptr[i] = ex; g_cursor[i] = ex; }
    if (i == NN - 1) g_rowptr[NN] = base + s[t];
}

__global__ void k_scatter(const int* __restrict__ ei) {
    int e = blockIdx.x * blockDim.x + threadIdx.x;
    if (e >= EE) return;
    int s = ei[e];
    int d = ei[EE + e];
    int p = atomicAdd(&g_cursor[d], 1);
    g_col[p] = s;
}

// ---------------- BN stats -> folded affine, re-zero accumulators ----------------
__global__ void k_bnstats(const float* __restrict__ gam, const float* __restrict__ bet) {
    int c = threadIdx.x;  // 64 threads
    float inv = 1.0f / (float)NN;
    float mu = g_bn[c] * inv;
    float var = g_bn[64 + c] * inv - mu * mu;
    float s = gam[c] * rsqrtf(var + 1e-5f);
    g_sc[c] = s;
    g_sh[c] = bet[c] - mu * s;
    g_bn[c] = 0.f;
    g_bn[64 + c] = 0.f;
}

// ================= FUSED: gather(agg, BN-fold) + MLP + BN partial sums =========
// 64-node tile per block, 256 threads. Double-buffered fp16 table (Hr -> Hw):
// no read/write aliasing across concurrently-running blocks.
__global__ __launch_bounds__(256) void k_fused(const float* __restrict__ wa,
                                               const float* __restrict__ ba,
                                               const float* __restrict__ wb,
                                               const float* __restrict__ bb,
                                               const float* __restrict__ epsp,
                                               const uint2* __restrict__ Hr,
                                               uint2* __restrict__ Hw,
                                               int fold, int wfp32) {
    __shared__ float sT[64][68];     // transposed tile sT[k][node]
    __shared__ float sW[64 * 64];
    __shared__ float sB[64];
    __shared__ float sRed[16][128];

    float* __restrict__ out = (float*)g_bufA4;

    int tid = threadIdx.x;
    int n0 = blockIdx.x * 64;
    float e1 = 1.0f + *epsp;

    // ---- phase 0: gather + fold ----
    {
        int hw = tid >> 4;       // half-warp id 0..15
        int li = tid & 15;       // lane within half-warp: 4 channels
        float4 fsc, fsh;
        if (fold) {
            fsc = *(const float4*)&g_sc[li * 4];
            fsh = *(const float4*)&g_sh[li * 4];
        }
#pragma unroll
        for (int rr = 0; rr < 4; rr++) {
            int r = hw + rr * 16;
            int node = n0 + r;
            float4 a0 = make_float4(0.f, 0.f, 0.f, 0.f);
            if (node < NN) {
                uint2 sv = Hr[node * 16 + li];
                float2 s0 = __half22float2(*(const __half2*)&sv.x);
                float2 s1 = __half22float2(*(const __half2*)&sv.y);
                a0 = make_float4(e1 * s0.x, e1 * s0.y, e1 * s1.x, e1 * s1.y);
                float4 a1 = make_float4(0.f, 0.f, 0.f, 0.f);
                int s = g_rowptr[node], e = g_rowptr[node + 1];
                int j = s;
                for (; j + 1 < e; j += 2) {
                    int m0 = __ldg(&g_col[j]);
                    int m1 = __ldg(&g_col[j + 1]);
                    uint2 v0 = Hr[m0 * 16 + li];
                    uint2 v1 = Hr[m1 * 16 + li];
                    float2 p0 = __half22float2(*(const __half2*)&v0.x);
                    float2 p1 = __half22float2(*(const __half2*)&v0.y);
                    float2 q0 = __half22float2(*(const __half2*)&v1.x);
                    float2 q1 = __half22float2(*(const __half2*)&v1.y);
                    a0.x += p0.x; a0.y += p0.y; a0.z += p1.x; a0.w += p1.y;
                    a1.x += q0.x; a1.y += q0.y; a1.z += q1.x; a1.w += q1.y;
                }
                if (j < e) {
                    int m0 = __ldg(&g_col[j]);
                    uint2 v0 = Hr[m0 * 16 + li];
                    float2 p0 = __half22float2(*(const __half2*)&v0.x);
                    float2 p1 = __half22float2(*(const __half2*)&v0.y);
                    a0.x += p0.x; a0.y += p0.y; a0.z += p1.x; a0.w += p1.y;
                }
                a0.x += a1.x; a0.y += a1.y; a0.z += a1.z; a0.w += a1.w;
                if (fold) {
                    float coef = e1 + (float)(e - s);
                    a0.x = fmaf(a0.x, fsc.x, coef * fsh.x);
                    a0.y = fmaf(a0.y, fsc.y, coef * fsh.y);
                    a0.z = fmaf(a0.z, fsc.z, coef * fsh.z);
                    a0.w = fmaf(a0.w, fsc.w, coef * fsh.w);
                }
            }
            sT[4 * li + 0][r] = a0.x;
            sT[4 * li + 1][r] = a0.y;
            sT[4 * li + 2][r] = a0.z;
            sT[4 * li + 3][r] = a0.w;
        }
    }
    for (int idx = tid; idx < 4096; idx += 256) sW[idx] = wa[idx];
    if (tid < 64) sB[tid] = ba[tid];
    __syncthreads();

    int tx = tid & 15;   // channel quad
    int ty = tid >> 4;   // node quad

    unsigned long long accP[4][2];
#pragma unroll
    for (int i = 0; i < 4; i++) { accP[i][0] = 0ULL; accP[i][1] = 0ULL; }

#pragma unroll 16
    for (int k = 0; k < 64; k++) {
        float4 a = *(const float4*)&sT[k][ty * 4];
        ulonglong2 b2 = *(const ulonglong2*)(sW + k * 64 + tx * 4);
        float av[4] = {a.x, a.y, a.z, a.w};
#pragma unroll
        for (int i = 0; i < 4; i++) {
            unsigned long long aa = pk2(av[i], av[i]);
            accP[i][0] = ffma2(aa, b2.x, accP[i][0]);
            accP[i][1] = ffma2(aa, b2.y, accP[i][1]);
        }
    }
    __syncthreads();  // all reads of sT/sW done

    // mid = relu(acc + ba), stored transposed back into sT
    {
        float m[4][4];
#pragma unroll
        for (int i = 0; i < 4; i++) {
            upk2(accP[i][0], m[i][0], m[i][1]);
            upk2(accP[i][1], m[i][2], m[i][3]);
        }
#pragma unroll
        for (int j = 0; j < 4; j++) {
            float bias = sB[4 * tx + j];
            float4 w;
            w.x = fmaxf(m[0][j] + bias, 0.f);
            w.y = fmaxf(m[1][j] + bias, 0.f);
            w.z = fmaxf(m[2][j] + bias, 0.f);
            w.w = fmaxf(m[3][j] + bias, 0.f);
            *(float4*)&sT[4 * tx + j][4 * ty] = w;
        }
    }
    for (int idx = tid; idx < 4096; idx += 256) sW[idx] = wb[idx];
    if (tid < 64) sB[tid] = bb[tid];
    __syncthreads();

#pragma unroll
    for (int i = 0; i < 4; i++) { accP[i][0] = 0ULL; accP[i][1] = 0ULL; }

#pragma unroll 16
    for (int k = 0; k < 64; k++) {
        float4 a = *(const float4*)&sT[k][ty * 4];
        ulonglong2 b2 = *(const ulonglong2*)(sW + k * 64 + tx * 4);
        float av[4] = {a.x, a.y, a.z, a.w};
#pragma unroll
        for (int i = 0; i < 4; i++) {
            unsigned long long aa = pk2(av[i], av[i]);
            accP[i][0] = ffma2(aa, b2.x, accP[i][0]);
            accP[i][1] = ffma2(aa, b2.y, accP[i][1]);
        }
    }

    // out = relu(acc2 + bb): fp16 table write + optional fp32 write + BN partials
    float m2[4][4];
#pragma unroll
    for (int i = 0; i < 4; i++) {
        upk2(accP[i][0], m2[i][0], m2[i][1]);
        upk2(accP[i][1], m2[i][2], m2[i][3]);
    }
    float psum[4] = {0.f, 0.f, 0.f, 0.f};
    float psq[4] = {0.f, 0.f, 0.f, 0.f};
#pragma unroll
    for (int i = 0; i < 4; i++) {
        int node = n0 + 4 * ty + i;
        float o[4];
#pragma unroll
        for (int j = 0; j < 4; j++) o[j] = fmaxf(m2[i][j] + sB[4 * tx + j], 0.f);
        if (node < NN) {
            __half2 h0 = __floats2half2_rn(o[0], o[1]);
            __half2 h1 = __floats2half2_rn(o[2], o[3]);
            uint2 hv;
            hv.x = *(const unsigned int*)&h0;
            hv.y = *(const unsigned int*)&h1;
            Hw[node * 16 + tx] = hv;
            if (wfp32) {
                float4 ov = make_float4(o[0], o[1], o[2], o[3]);
                *(float4*)&out[node * 64 + 4 * tx] = ov;
            }
#pragma unroll
            for (int j = 0; j < 4; j++) {
                psum[j] += o[j];
                psq[j] = fmaf(o[j], o[j], psq[j]);
            }
        }
    }
#pragma unroll
    for (int j = 0; j < 4; j++) {
        sRed[ty][4 * tx + j] = psum[j];
        sRed[ty][64 + 4 * tx + j] = psq[j];
    }
    __syncthreads();
    if (tid < 128) {
        float s = 0.f;
#pragma unroll
        for (int r = 0; r < 16; r++) s += sRed[r][tid];
        atomicAdd(&g_bn[tid], s);
    }
}

// ---------------- fused pooling (mean+max, BN folded) + FC + log_softmax ----------------
__global__ void k_pool(const float* __restrict__ wfc, const float* __restrict__ bfc,
                       float* __restrict__ outp) {
    int g = blockIdx.x;
    int tid = threadIdx.x;  // 256 threads
    int r = tid >> 6;       // 0..3
    int c = tid & 63;
    __shared__ float ssum[4][64], smax[4][64], smin[4][64];
    __shared__ float sm[128];
    __shared__ float sz[6];
    const float* __restrict__ h = (const float*)g_bufA4;

    int s = g_gs[g], e = g_ge[g];
    float sum = 0.f, mx = -3.4e38f, mn = 3.4e38f;
    if (s >= 0) {
        for (int i = s + r; i <= e; i += 4) {
            float v = h[i * 64 + c];
            sum += v;
            mx = fmaxf(mx, v);
            mn = fminf(mn, v);
        }
    }
    ssum[r][c] = sum; smax[r][c] = mx; smin[r][c] = mn;
    __syncthreads();
    if (r == 0) {
        if (s >= 0) {
            float S = ssum[0][c] + ssum[1][c] + ssum[2][c] + ssum[3][c];
            float MX = fmaxf(fmaxf(smax[0][c], smax[1][c]), fmaxf(smax[2][c], smax[3][c]));
            float MN = fminf(fminf(smin[0][c], smin[1][c]), fminf(smin[2][c], smin[3][c]));
            float cnt = (float)(e - s + 1);
            float sc = g_sc[c], sh = g_sh[c];
            sm[c] = fmaf(sc, S / cnt, sh);
            sm[64 + c] = (sc >= 0.f) ? fmaf(sc, MX, sh) : fmaf(sc, MN, sh);
        } else {
            sm[c] = 0.f;
            sm[64 + c] = 0.f;
        }
    }
    __syncthreads();
    if (tid < 6) {
        float z = bfc[tid];
#pragma unroll 8
        for (int k = 0; k < 128; k++) z = fmaf(sm[k], wfc[k * 6 + tid], z);
        sz[tid] = z;
    }
    __syncthreads();
    if (tid == 0) {
        float m = sz[0];
#pragma unroll
        for (int j = 1; j < 6; j++) m = fmaxf(m, sz[j]);
        float se = 0.f;
#pragma unroll
        for (int j = 0; j < 6; j++) se += expf(sz[j] - m);
        float lse = m + logf(se);
#pragma unroll
        for (int j = 0; j < 6; j++) outp[g * 6 + j] = sz[j] - lse;
    }
}

// ---------------- launch ----------------
extern "C" void kernel_launch(void* const* d_in, const int* in_sizes, int n_in,
                              void* d_out, int out_size) {
    const float* x = (const float*)d_in[0];
    const int* ei = (const int*)d_in[1];
    const int* batch = (const int*)d_in[2];
    const float* w1a = (const float*)d_in[3];
    const float* b1a = (const float*)d_in[4];
    const float* w1b = (const float*)d_in[5];
    const float* b1b = (const float*)d_in[6];
    const float* w2a = (const float*)d_in[7];
    const float* b2a = (const float*)d_in[8];
    const float* w2b = (const float*)d_in[9];
    const float* b2b = (const float*)d_in[10];
    const float* w3a = (const float*)d_in[11];
    const float* b3a = (const float*)d_in[12];
    const float* w3b = (const float*)d_in[13];
    const float* b3b = (const float*)d_in[14];
    const float* eps1 = (const float*)d_in[15];
    const float* g1 = (const float*)d_in[16];
    const float* be1 = (const float*)d_in[17];
    const float* eps2 = (const float*)d_in[18];
    const float* g2 = (const float*)d_in[19];
    const float* be2 = (const float*)d_in[20];
    const float* eps3 = (const float*)d_in[21];
    const float* g3 = (const float*)d_in[22];
    const float* be3 = (const float*)d_in[23];
    const float* eps4 = (const float*)d_in[24];
    const float* g4 = (const float*)d_in[25];
    const float* be4 = (const float*)d_in[26];
    const float* wfc = (const float*)d_in[27];
    const float* bfc = (const float*)d_in[28];
    float* out = (float*)d_out;

    const int NB_E = (EE + 255) / 256;           // 12500 (== NN*32/256)
    const int NB_MLP = (NN + 63) / 64;           // 1563

    k_init<<<NBLK, 256>>>();
    k_toh_hist<<<NB_E, 256>>>((const float2*)x, ei);
    k_bounds_bsum<<<NBLK, 256>>>(batch);
    k_scanb<<<1, 512>>>();
    k_scan2<<<NBLK, 256>>>();
    k_scatter<<<NB_E, 256>>>(ei);

    // resolve device-global table addresses on host (graph-capturable: no sync)
    uint2 *h0, *h1;
    cudaGetSymbolAddress((void**)&h0, g_bufH0);
    cudaGetSymbolAddress((void**)&h1, g_bufH1);

    struct Layer {
        const float *wa, *ba, *wb, *bb, *eps, *g, *be;
    } layers[4] = {
        {w1a, b1a, w1b, b1b, eps1, g1, be1},
        {w2a, b2a, w2b, b2b, eps2, g2, be2},
        {w3a, b3a, w3b, b3b, eps3, g3, be3},
        {w3a, b3a, w3b, b3b, eps4, g4, be4},  // conv4 reuses nn3 weights
    };

    for (int l = 0; l < 4; l++) {
        const uint2* Hr = (l & 1) ? h1 : h0;
        uint2* Hw = (l & 1) ? h0 : h1;
        k_fused<<<NB_MLP, 256>>>(layers[l].wa, layers[l].ba, layers[l].wb, layers[l].bb,
                                 layers[l].eps, Hr, Hw, (l == 0) ? 0 : 1, (l == 3) ? 1 : 0);
        k_bnstats<<<1, 64>>>(layers[l].g, layers[l].be);
    }

    k_pool<<<GG, 256>>>(wfc, bfc, out);
}